// round 13
// baseline (speedup 1.0000x reference)
#include <cuda_runtime.h>
#include <cuda_fp16.h>
#include <cstdint>
#include <math.h>

// ---------------------------------------------------------------------------
// Problem constants
// ---------------------------------------------------------------------------
#define BATCH 4
#define SEQ   4096
#define HID   1024
#define NH    16
#define DH    64
#define M_TOT (BATCH * SEQ)   // 16384
#define N_TOT (3 * HID)       // 3072
#define K_TOT HID             // 1024

// Scratch (device globals: allocation-free rule)
__device__ __half g_qkv[(size_t)M_TOT * N_TOT];  // 96 MB
__device__ __half g_ah[(size_t)M_TOT * K_TOT];   // 32 MB
__device__ __half g_wh[(size_t)N_TOT * K_TOT];   // 6 MB

// ---------------------------------------------------------------------------
// Helpers (sm_80-era PTX only)
// ---------------------------------------------------------------------------
__device__ __forceinline__ uint32_t smem_u32(const void* p) {
    uint32_t a;
    asm("{ .reg .u64 t; cvta.to.shared.u64 t, %1; cvt.u32.u64 %0, t; }"
        : "=r"(a) : "l"(p));
    return a;
}

__device__ __forceinline__ void cp_async16(uint32_t s, const void* g) {
    asm volatile("cp.async.cg.shared.global [%0], [%1], 16;" :: "r"(s), "l"(g) : "memory");
}

__device__ __forceinline__ void ldsm_x4(uint32_t& r0, uint32_t& r1,
                                        uint32_t& r2, uint32_t& r3, uint32_t addr) {
    asm volatile("ldmatrix.sync.aligned.m8n8.x4.shared.b16 {%0,%1,%2,%3}, [%4];"
                 : "=r"(r0), "=r"(r1), "=r"(r2), "=r"(r3) : "r"(addr));
}

__device__ __forceinline__ void mma_fp16(float* c, const uint32_t* a,
                                         uint32_t b0, uint32_t b1) {
    asm volatile(
        "mma.sync.aligned.m16n8k16.row.col.f32.f16.f16.f32 "
        "{%0,%1,%2,%3}, {%4,%5,%6,%7}, {%8,%9}, {%0,%1,%2,%3};"
        : "+f"(c[0]), "+f"(c[1]), "+f"(c[2]), "+f"(c[3])
        : "r"(a[0]), "r"(a[1]), "r"(a[2]), "r"(a[3]), "r"(b0), "r"(b1));
}

// ---------------------------------------------------------------------------
// Conversion: A(fp32) -> fp16, W(fp32) -> fp16
// ---------------------------------------------------------------------------
#define N4_A ((size_t)M_TOT * K_TOT / 4)
#define N4_W ((size_t)N_TOT * K_TOT / 4)
#define N4_TOTAL (N4_A + N4_W)

__global__ __launch_bounds__(256) void convert_kernel(
    const float* __restrict__ A, const float* __restrict__ W)
{
    size_t idx = (size_t)blockIdx.x * blockDim.x + threadIdx.x;
    if (idx >= N4_TOTAL) return;

    if (idx < N4_A) {
        float4 v = ((const float4*)A)[idx];
        __half h[4] = { __float2half_rn(v.x), __float2half_rn(v.y),
                        __float2half_rn(v.z), __float2half_rn(v.w) };
        *(uint2*)(g_ah + idx * 4) = *(uint2*)h;
    } else {
        size_t j = idx - N4_A;
        float4 v = ((const float4*)W)[j];
        __half h[4] = { __float2half_rn(v.x), __float2half_rn(v.y),
                        __float2half_rn(v.z), __float2half_rn(v.w) };
        *(uint2*)(g_wh + j * 4) = *(uint2*)h;
    }
}

// ---------------------------------------------------------------------------
// GEMM fp16 (R12 form — at the legacy-HMMA hardware rate; leave alone):
// CTA 128x128, 4 warps of 64x64, BK=64, 3 stages, 2 CTAs/SM.
// ---------------------------------------------------------------------------
#define BK      64
#define KITERS  (K_TOT / BK)     // 16
#define STAGES  3
#define ROWB    144
#define TILEB   (128 * ROWB)     // 18432
#define STAGEB  (2 * TILEB)      // 36864
#define GEMM_SMEM (STAGES * STAGEB)  // 110592

__global__ void __launch_bounds__(128, 2) gemm_qkv_mma(
    const __half* __restrict__ Ah, const __half* __restrict__ Wh,
    const float* __restrict__ bias, __half* __restrict__ C)
{
    extern __shared__ char smem[];
    const uint32_t sb = smem_u32(smem);
    const int t    = threadIdx.x;
    const int wid  = t >> 5;
    const int lane = t & 31;
    const int m0 = blockIdx.y * 128;
    const int n0 = blockIdx.x * 128;
    const int wm = (wid & 1) * 64;
    const int wn = (wid >> 1) * 64;

    const char* aptr = (const char*)(Ah + (size_t)(m0 + (t >> 3)) * K_TOT) + (t & 7) * 16;
    const char* wptr = (const char*)(Wh + (size_t)(n0 + (t >> 3)) * K_TOT) + (t & 7) * 16;
    const uint32_t so0 = (uint32_t)((t >> 3) * ROWB + (t & 7) * 16);

    auto load_stage = [&](int s) {
        const uint32_t dst = sb + (s % STAGES) * STAGEB + so0;
        const int koff = s * (BK * 2);
#pragma unroll
        for (int i = 0; i < 8; i++) {
            cp_async16(dst + (uint32_t)(i * 16 * ROWB),
                       aptr + (size_t)i * 16 * K_TOT * 2 + koff);
            cp_async16(dst + TILEB + (uint32_t)(i * 16 * ROWB),
                       wptr + (size_t)i * 16 * K_TOT * 2 + koff);
        }
    };

    float acc[4][8][4];
#pragma unroll
    for (int mt = 0; mt < 4; mt++)
#pragma unroll
        for (int nt = 0; nt < 8; nt++)
#pragma unroll
            for (int q = 0; q < 4; q++) acc[mt][nt][q] = 0.0f;

#pragma unroll
    for (int s = 0; s < STAGES - 1; s++) {
        load_stage(s);
        asm volatile("cp.async.commit_group;" ::: "memory");
    }

    const int lrow  = lane & 15;
    const int lkoff = (lane >> 4) * 16;

    for (int kit = 0; kit < KITERS; kit++) {
        asm volatile("cp.async.wait_group %0;" :: "n"(STAGES - 2) : "memory");
        __syncthreads();

        if (kit + STAGES - 1 < KITERS) load_stage(kit + STAGES - 1);
        asm volatile("cp.async.commit_group;" ::: "memory");

        const uint32_t bufb = sb + (kit % STAGES) * STAGEB;
        const uint32_t aH = bufb;
        const uint32_t wH = bufb + TILEB;

#pragma unroll
        for (int ks = 0; ks < 4; ks++) {
            const uint32_t kb = (uint32_t)(ks * 32 + lkoff);

            uint32_t af[4][4];
#pragma unroll
            for (int mt = 0; mt < 4; mt++) {
                const uint32_t ro = (uint32_t)((wm + mt * 16 + lrow) * ROWB) + kb;
                ldsm_x4(af[mt][0], af[mt][1], af[mt][2], af[mt][3], aH + ro);
            }

            uint32_t bh0[8], bh1[8];
#pragma unroll
            for (int np = 0; np < 4; np++) {
                const uint32_t ro = (uint32_t)((wn + np * 16 + lrow) * ROWB) + kb;
                uint32_t r0, r1, r2, r3;
                ldsm_x4(r0, r1, r2, r3, wH + ro);
                bh0[np * 2] = r0; bh1[np * 2] = r2;
                bh0[np * 2 + 1] = r1; bh1[np * 2 + 1] = r3;
            }

#pragma unroll
            for (int mt = 0; mt < 4; mt++)
#pragma unroll
                for (int nt = 0; nt < 8; nt++)
                    mma_fp16(acc[mt][nt], af[mt], bh0[nt], bh1[nt]);
        }
    }

#pragma unroll
    for (int mt = 0; mt < 4; mt++) {
        const int r = m0 + wm + mt * 16 + (lane >> 2);
#pragma unroll
        for (int nt = 0; nt < 8; nt++) {
            const int cc = n0 + wn + nt * 8 + (lane & 3) * 2;
            const float bx = __ldg(bias + cc);
            const float by = __ldg(bias + cc + 1);
            __half2 h0, h1;
            h0.x = __float2half_rn(acc[mt][nt][0] + bx);
            h0.y = __float2half_rn(acc[mt][nt][1] + by);
            h1.x = __float2half_rn(acc[mt][nt][2] + bx);
            h1.y = __float2half_rn(acc[mt][nt][3] + by);
            *(__half2*)(C + (size_t)r * N_TOT + cc)       = h0;
            *(__half2*)(C + (size_t)(r + 8) * N_TOT + cc) = h1;
        }
    }
}

// ---------------------------------------------------------------------------
// Attention v3: warp-per-position; k,v converted ONCE to fp32 smem
// (cooperative), q kept fp16 in registers. QK/PV = pure LDS.128 + FFMA.
// Per-lane converts drop ~1030 -> ~96.
// Per-warp smem: kf[16][68] + vf[16][68] + sw[16][17] = 2448 floats (9792B).
// ---------------------------------------------------------------------------
__global__ __launch_bounds__(128) void attn_kernel(
    const __half* __restrict__ qkv, const float* __restrict__ mask,
    float* __restrict__ out)
{
    __shared__ __align__(16) float sm[4][2448];

    const int wid  = threadIdx.x >> 5;
    const int lane = threadIdx.x & 31;
    const int p = blockIdx.x * 4 + wid;

    float* kf = sm[wid];          // [16][68]
    float* vf = kf + 1088;        // [16][68]
    float* sw = vf + 1088;        // [16][17]

    const int h  = lane >> 1;
    const int gh = lane & 1;

    const uint4* src = (const uint4*)(qkv + (size_t)p * N_TOT);

    // q row h -> registers (fp16 packed, 8 uint4)
    uint4 qreg[8];
#pragma unroll
    for (int i = 0; i < 8; i++) qreg[i] = src[h * 8 + i];

    // cooperative k convert: 128 uint4, 4 per lane
#pragma unroll
    for (int i = lane; i < 128; i += 32) {
        uint4 raw = src[128 + i];
        const __half2* hp = (const __half2*)&raw;
        float* dst = kf + (i >> 3) * 68 + (i & 7) * 8;
        float2 f0 = __half22float2(hp[0]), f1 = __half22float2(hp[1]);
        float2 f2 = __half22float2(hp[2]), f3 = __half22float2(hp[3]);
        float4 w0 = make_float4(f0.x, f0.y, f1.x, f1.y);
        float4 w1 = make_float4(f2.x, f2.y, f3.x, f3.y);
        *(float4*)dst       = w0;
        *(float4*)(dst + 4) = w1;
    }
    // cooperative v convert
#pragma unroll
    for (int i = lane; i < 128; i += 32) {
        uint4 raw = src[256 + i];
        const __half2* hp = (const __half2*)&raw;
        float* dst = vf + (i >> 3) * 68 + (i & 7) * 8;
        float2 f0 = __half22float2(hp[0]), f1 = __half22float2(hp[1]);
        float2 f2 = __half22float2(hp[2]), f3 = __half22float2(hp[3]);
        float4 w0 = make_float4(f0.x, f0.y, f1.x, f1.y);
        float4 w1 = make_float4(f2.x, f2.y, f3.x, f3.y);
        *(float4*)dst       = w0;
        *(float4*)(dst + 4) = w1;
    }
    __syncwarp();

    // ---- QK: 8 dot products of length 64 (fp32 smem k) ----
    float s[8];
#pragma unroll
    for (int gi = 0; gi < 8; gi++) s[gi] = 0.0f;

#pragma unroll
    for (int d8 = 0; d8 < 8; d8++) {
        const __half2* qh2 = (const __half2*)&qreg[d8];
        float qf[8];
#pragma unroll
        for (int j = 0; j < 4; j++) {
            float2 f = __half22float2(qh2[j]);
            qf[2 * j] = f.x; qf[2 * j + 1] = f.y;
        }
#pragma unroll
        for (int gi = 0; gi < 8; gi++) {
            const float* kp = kf + (gh * 8 + gi) * 68 + d8 * 8;
            float4 k0 = *(const float4*)kp;
            float4 k1 = *(const float4*)(kp + 4);
            s[gi] = fmaf(qf[0], k0.x, s[gi]);
            s[gi] = fmaf(qf[1], k0.y, s[gi]);
            s[gi] = fmaf(qf[2], k0.z, s[gi]);
            s[gi] = fmaf(qf[3], k0.w, s[gi]);
            s[gi] = fmaf(qf[4], k1.x, s[gi]);
            s[gi] = fmaf(qf[5], k1.y, s[gi]);
            s[gi] = fmaf(qf[6], k1.z, s[gi]);
            s[gi] = fmaf(qf[7], k1.w, s[gi]);
        }
    }

    // scale + mask
    {
        const float* mrow = mask + (size_t)p * (NH * NH) + h * NH + gh * 8;
        float4 m0 = *(const float4*)mrow;
        float4 m1 = *(const float4*)(mrow + 4);
        const float mf[8] = {m0.x, m0.y, m0.z, m0.w, m1.x, m1.y, m1.z, m1.w};
#pragma unroll
        for (int gi = 0; gi < 8; gi++) s[gi] = s[gi] * 0.125f + mf[gi];
    }

    // ---- softmax across 16-wide row (2 lanes per row) ----
    float mx = s[0];
#pragma unroll
    for (int gi = 1; gi < 8; gi++) mx = fmaxf(mx, s[gi]);
    mx = fmaxf(mx, __shfl_xor_sync(0xffffffff, mx, 1));

    float e[8], sum = 0.0f;
#pragma unroll
    for (int gi = 0; gi < 8; gi++) { e[gi] = __expf(s[gi] - mx); sum += e[gi]; }
    sum += __shfl_xor_sync(0xffffffff, sum, 1);
    const float inv = 1.0f / sum;

#pragma unroll
    for (int gi = 0; gi < 8; gi++) sw[h * 17 + gh * 8 + gi] = e[gi] * inv;
    __syncwarp();

    // ---- PV: lane computes out[h][gh*32 .. gh*32+31] (fp32 smem v) ----
    float acc[32];
#pragma unroll
    for (int d = 0; d < 32; d++) acc[d] = 0.0f;

#pragma unroll
    for (int g = 0; g < 16; g++) {
        const float wv = sw[h * 17 + g];
        const float* vp = vf + g * 68 + gh * 32;
#pragma unroll
        for (int d8 = 0; d8 < 4; d8++) {
            float4 v0 = *(const float4*)(vp + d8 * 8);
            float4 v1 = *(const float4*)(vp + d8 * 8 + 4);
            acc[d8 * 8 + 0] = fmaf(wv, v0.x, acc[d8 * 8 + 0]);
            acc[d8 * 8 + 1] = fmaf(wv, v0.y, acc[d8 * 8 + 1]);
            acc[d8 * 8 + 2] = fmaf(wv, v0.z, acc[d8 * 8 + 2]);
            acc[d8 * 8 + 3] = fmaf(wv, v0.w, acc[d8 * 8 + 3]);
            acc[d8 * 8 + 4] = fmaf(wv, v1.x, acc[d8 * 8 + 4]);
            acc[d8 * 8 + 5] = fmaf(wv, v1.y, acc[d8 * 8 + 5]);
            acc[d8 * 8 + 6] = fmaf(wv, v1.z, acc[d8 * 8 + 6]);
            acc[d8 * 8 + 7] = fmaf(wv, v1.w, acc[d8 * 8 + 7]);
        }
    }

    float* orow = out + (size_t)p * HID + h * DH + gh * 32;
#pragma unroll
    for (int d4 = 0; d4 < 8; d4++) {
        float4 o;
        o.x = acc[4 * d4]; o.y = acc[4 * d4 + 1];
        o.z = acc[4 * d4 + 2]; o.w = acc[4 * d4 + 3];
        *(float4*)(orow + 4 * d4) = o;
    }
}

// ---------------------------------------------------------------------------
// Launch — inputs: 0=query, 1=key, 2=value, 3=attn_mask, 4=W_qkv, 5=b_qkv
// ---------------------------------------------------------------------------
extern "C" void kernel_launch(void* const* d_in, const int* in_sizes, int n_in,
                              void* d_out, int out_size)
{
    const float* query = (const float*)d_in[0];
    const float* mask  = (const float*)d_in[3];
    const float* W     = (const float*)d_in[4];
    const float* bias  = (const float*)d_in[5];
    float* out = (float*)d_out;

    __half *qkv, *ah, *wh;
    cudaGetSymbolAddress((void**)&qkv, g_qkv);
    cudaGetSymbolAddress((void**)&ah, g_ah);
    cudaGetSymbolAddress((void**)&wh, g_wh);

    const int cvt_blocks = (int)((N4_TOTAL + 255) / 256);
    convert_kernel<<<cvt_blocks, 256>>>(query, W);

    cudaFuncSetAttribute(gemm_qkv_mma, cudaFuncAttributeMaxDynamicSharedMemorySize,
                         GEMM_SMEM);
    dim3 ggrid(N_TOT / 128, M_TOT / 128);  // (24, 128)
    gemm_qkv_mma<<<ggrid, 128, GEMM_SMEM>>>(ah, wh, bias, qkv);

    attn_kernel<<<M_TOT / 4, 128>>>(qkv, mask, out);
}

// round 14
// speedup vs baseline: 1.0411x; 1.0411x over previous
#include <cuda_runtime.h>
#include <cuda_fp16.h>
#include <cstdint>
#include <math.h>

// ---------------------------------------------------------------------------
// Problem constants
// ---------------------------------------------------------------------------
#define BATCH 4
#define SEQ   4096
#define HID   1024
#define NH    16
#define DH    64
#define M_TOT (BATCH * SEQ)   // 16384
#define N_TOT (3 * HID)       // 3072
#define K_TOT HID             // 1024

// Scratch (device globals: allocation-free rule)
__device__ __half g_qkv[(size_t)M_TOT * N_TOT];  // 96 MB
__device__ __half g_ah[(size_t)M_TOT * K_TOT];   // 32 MB
__device__ __half g_wh[(size_t)N_TOT * K_TOT];   // 6 MB

// ---------------------------------------------------------------------------
// Helpers (sm_80-era PTX only)
// ---------------------------------------------------------------------------
__device__ __forceinline__ uint32_t smem_u32(const void* p) {
    uint32_t a;
    asm("{ .reg .u64 t; cvta.to.shared.u64 t, %1; cvt.u32.u64 %0, t; }"
        : "=r"(a) : "l"(p));
    return a;
}

__device__ __forceinline__ void cp_async16(uint32_t s, const void* g) {
    asm volatile("cp.async.cg.shared.global [%0], [%1], 16;" :: "r"(s), "l"(g) : "memory");
}

__device__ __forceinline__ void ldsm_x4(uint32_t& r0, uint32_t& r1,
                                        uint32_t& r2, uint32_t& r3, uint32_t addr) {
    asm volatile("ldmatrix.sync.aligned.m8n8.x4.shared.b16 {%0,%1,%2,%3}, [%4];"
                 : "=r"(r0), "=r"(r1), "=r"(r2), "=r"(r3) : "r"(addr));
}

__device__ __forceinline__ void mma_fp16(float* c, const uint32_t* a,
                                         uint32_t b0, uint32_t b1) {
    asm volatile(
        "mma.sync.aligned.m16n8k16.row.col.f32.f16.f16.f32 "
        "{%0,%1,%2,%3}, {%4,%5,%6,%7}, {%8,%9}, {%0,%1,%2,%3};"
        : "+f"(c[0]), "+f"(c[1]), "+f"(c[2]), "+f"(c[3])
        : "r"(a[0]), "r"(a[1]), "r"(a[2]), "r"(a[3]), "r"(b0), "r"(b1));
}

// ---------------------------------------------------------------------------
// Conversion: A(fp32) -> fp16, W(fp32) -> fp16
// ---------------------------------------------------------------------------
#define N4_A ((size_t)M_TOT * K_TOT / 4)
#define N4_W ((size_t)N_TOT * K_TOT / 4)
#define N4_TOTAL (N4_A + N4_W)

__global__ __launch_bounds__(256) void convert_kernel(
    const float* __restrict__ A, const float* __restrict__ W)
{
    size_t idx = (size_t)blockIdx.x * blockDim.x + threadIdx.x;
    if (idx >= N4_TOTAL) return;

    if (idx < N4_A) {
        float4 v = ((const float4*)A)[idx];
        __half h[4] = { __float2half_rn(v.x), __float2half_rn(v.y),
                        __float2half_rn(v.z), __float2half_rn(v.w) };
        *(uint2*)(g_ah + idx * 4) = *(uint2*)h;
    } else {
        size_t j = idx - N4_A;
        float4 v = ((const float4*)W)[j];
        __half h[4] = { __float2half_rn(v.x), __float2half_rn(v.y),
                        __float2half_rn(v.z), __float2half_rn(v.w) };
        *(uint2*)(g_wh + j * 4) = *(uint2*)h;
    }
}

// ---------------------------------------------------------------------------
// GEMM fp16 (R12 form — at the legacy-HMMA dispatch rate; unchanged):
// CTA 128x128, 4 warps of 64x64, BK=64, 3 stages, 2 CTAs/SM.
// ---------------------------------------------------------------------------
#define BK      64
#define KITERS  (K_TOT / BK)     // 16
#define STAGES  3
#define ROWB    144
#define TILEB   (128 * ROWB)     // 18432
#define STAGEB  (2 * TILEB)      // 36864
#define GEMM_SMEM (STAGES * STAGEB)  // 110592

__global__ void __launch_bounds__(128, 2) gemm_qkv_mma(
    const __half* __restrict__ Ah, const __half* __restrict__ Wh,
    const float* __restrict__ bias, __half* __restrict__ C)
{
    extern __shared__ char smem[];
    const uint32_t sb = smem_u32(smem);
    const int t    = threadIdx.x;
    const int wid  = t >> 5;
    const int lane = t & 31;
    const int m0 = blockIdx.y * 128;
    const int n0 = blockIdx.x * 128;
    const int wm = (wid & 1) * 64;
    const int wn = (wid >> 1) * 64;

    const char* aptr = (const char*)(Ah + (size_t)(m0 + (t >> 3)) * K_TOT) + (t & 7) * 16;
    const char* wptr = (const char*)(Wh + (size_t)(n0 + (t >> 3)) * K_TOT) + (t & 7) * 16;
    const uint32_t so0 = (uint32_t)((t >> 3) * ROWB + (t & 7) * 16);

    auto load_stage = [&](int s) {
        const uint32_t dst = sb + (s % STAGES) * STAGEB + so0;
        const int koff = s * (BK * 2);
#pragma unroll
        for (int i = 0; i < 8; i++) {
            cp_async16(dst + (uint32_t)(i * 16 * ROWB),
                       aptr + (size_t)i * 16 * K_TOT * 2 + koff);
            cp_async16(dst + TILEB + (uint32_t)(i * 16 * ROWB),
                       wptr + (size_t)i * 16 * K_TOT * 2 + koff);
        }
    };

    float acc[4][8][4];
#pragma unroll
    for (int mt = 0; mt < 4; mt++)
#pragma unroll
        for (int nt = 0; nt < 8; nt++)
#pragma unroll
            for (int q = 0; q < 4; q++) acc[mt][nt][q] = 0.0f;

#pragma unroll
    for (int s = 0; s < STAGES - 1; s++) {
        load_stage(s);
        asm volatile("cp.async.commit_group;" ::: "memory");
    }

    const int lrow  = lane & 15;
    const int lkoff = (lane >> 4) * 16;

    for (int kit = 0; kit < KITERS; kit++) {
        asm volatile("cp.async.wait_group %0;" :: "n"(STAGES - 2) : "memory");
        __syncthreads();

        if (kit + STAGES - 1 < KITERS) load_stage(kit + STAGES - 1);
        asm volatile("cp.async.commit_group;" ::: "memory");

        const uint32_t bufb = sb + (kit % STAGES) * STAGEB;
        const uint32_t aH = bufb;
        const uint32_t wH = bufb + TILEB;

#pragma unroll
        for (int ks = 0; ks < 4; ks++) {
            const uint32_t kb = (uint32_t)(ks * 32 + lkoff);

            uint32_t af[4][4];
#pragma unroll
            for (int mt = 0; mt < 4; mt++) {
                const uint32_t ro = (uint32_t)((wm + mt * 16 + lrow) * ROWB) + kb;
                ldsm_x4(af[mt][0], af[mt][1], af[mt][2], af[mt][3], aH + ro);
            }

            uint32_t bh0[8], bh1[8];
#pragma unroll
            for (int np = 0; np < 4; np++) {
                const uint32_t ro = (uint32_t)((wn + np * 16 + lrow) * ROWB) + kb;
                uint32_t r0, r1, r2, r3;
                ldsm_x4(r0, r1, r2, r3, wH + ro);
                bh0[np * 2] = r0; bh1[np * 2] = r2;
                bh0[np * 2 + 1] = r1; bh1[np * 2 + 1] = r3;
            }

#pragma unroll
            for (int mt = 0; mt < 4; mt++)
#pragma unroll
                for (int nt = 0; nt < 8; nt++)
                    mma_fp16(acc[mt][nt], af[mt], bh0[nt], bh1[nt]);
        }
    }

#pragma unroll
    for (int mt = 0; mt < 4; mt++) {
        const int r = m0 + wm + mt * 16 + (lane >> 2);
#pragma unroll
        for (int nt = 0; nt < 8; nt++) {
            const int cc = n0 + wn + nt * 8 + (lane & 3) * 2;
            const float bx = __ldg(bias + cc);
            const float by = __ldg(bias + cc + 1);
            __half2 h0, h1;
            h0.x = __float2half_rn(acc[mt][nt][0] + bx);
            h0.y = __float2half_rn(acc[mt][nt][1] + by);
            h1.x = __float2half_rn(acc[mt][nt][2] + bx);
            h1.y = __float2half_rn(acc[mt][nt][3] + by);
            *(__half2*)(C + (size_t)r * N_TOT + cc)       = h0;
            *(__half2*)(C + (size_t)(r + 8) * N_TOT + cc) = h1;
        }
    }
}

// ---------------------------------------------------------------------------
// Attention v4: warp handles TWO positions (A,B), explicitly interleaved for
// ILP. cp.async smem fill (24 outstanding 16B). R8 math/order per position.
// Softmax weights exchanged via shfl_xor(1) — no sw smem.
// Smem: 4 warps x 2 pos x 3456 halfs = 55296 B -> 4 blocks/SM.
// ---------------------------------------------------------------------------
__global__ __launch_bounds__(128) void attn_kernel(
    const __half* __restrict__ qkv, const float* __restrict__ mask,
    float* __restrict__ out)
{
    __shared__ __align__(16) __half sm[4][2][3456];

    const int wid  = threadIdx.x >> 5;
    const int lane = threadIdx.x & 31;
    const int pA = blockIdx.x * 8 + wid * 2;
    const int pB = pA + 1;

    const uint32_t baseA = smem_u32(&sm[wid][0][0]);
    const uint32_t baseB = smem_u32(&sm[wid][1][0]);

    // cp.async qkv fill for both positions (12 chunks/lane each)
    {
        const char* srcA = (const char*)(qkv + (size_t)pA * N_TOT);
        const char* srcB = (const char*)(qkv + (size_t)pB * N_TOT);
#pragma unroll
        for (int i = lane; i < 384; i += 32) {
            const int e   = i * 8;
            const int arr = e >> 10;
            const int r   = e & 1023;
            const uint32_t off = (uint32_t)(arr * 2304 + (r >> 6) * 144 + (r & 63) * 2);
            cp_async16(baseA + off, srcA + i * 16);
            cp_async16(baseB + off, srcB + i * 16);
        }
        asm volatile("cp.async.commit_group;" ::: "memory");
    }

    const int h  = lane >> 1;
    const int gh = lane & 1;

    // mask prefetch (independent of cp.async)
    float mfA[8], mfB[8];
    {
        const float* mA = mask + (size_t)pA * (NH * NH) + h * NH + gh * 8;
        const float* mB = mask + (size_t)pB * (NH * NH) + h * NH + gh * 8;
        float4 a0 = *(const float4*)mA;
        float4 a1 = *(const float4*)(mA + 4);
        float4 b0 = *(const float4*)mB;
        float4 b1 = *(const float4*)(mB + 4);
        mfA[0]=a0.x; mfA[1]=a0.y; mfA[2]=a0.z; mfA[3]=a0.w;
        mfA[4]=a1.x; mfA[5]=a1.y; mfA[6]=a1.z; mfA[7]=a1.w;
        mfB[0]=b0.x; mfB[1]=b0.y; mfB[2]=b0.z; mfB[3]=b0.w;
        mfB[4]=b1.x; mfB[5]=b1.y; mfB[6]=b1.z; mfB[7]=b1.w;
    }

    asm volatile("cp.async.wait_group 0;" ::: "memory");
    __syncwarp();

    const __half* smA = &sm[wid][0][0];
    const __half* smB = &sm[wid][1][0];

    // ---- QK interleaved: sA[8], sB[8] ----
    float sA[8], sB[8];
#pragma unroll
    for (int gi = 0; gi < 8; gi++) { sA[gi] = 0.0f; sB[gi] = 0.0f; }

    const __half* qrA = smA + h * 72;
    const __half* qrB = smB + h * 72;
#pragma unroll
    for (int d8 = 0; d8 < 8; d8++) {
        uint4 qa = *(const uint4*)(qrA + d8 * 8);
        uint4 qb = *(const uint4*)(qrB + d8 * 8);
        const __half2* qa2 = (const __half2*)&qa;
        const __half2* qb2 = (const __half2*)&qb;
        float qfA[8], qfB[8];
#pragma unroll
        for (int j = 0; j < 4; j++) {
            float2 fa = __half22float2(qa2[j]);
            float2 fb = __half22float2(qb2[j]);
            qfA[2*j] = fa.x; qfA[2*j+1] = fa.y;
            qfB[2*j] = fb.x; qfB[2*j+1] = fb.y;
        }
#pragma unroll
        for (int gi = 0; gi < 8; gi++) {
            const __half* kA = smA + 1152 + (gh * 8 + gi) * 72 + d8 * 8;
            const __half* kB = smB + 1152 + (gh * 8 + gi) * 72 + d8 * 8;
            uint4 ka = *(const uint4*)kA;
            uint4 kb = *(const uint4*)kB;
            const __half2* ka2 = (const __half2*)&ka;
            const __half2* kb2 = (const __half2*)&kb;
#pragma unroll
            for (int j = 0; j < 4; j++) {
                float2 fa = __half22float2(ka2[j]);
                float2 fb = __half22float2(kb2[j]);
                sA[gi] += qfA[2*j] * fa.x + qfA[2*j+1] * fa.y;
                sB[gi] += qfB[2*j] * fb.x + qfB[2*j+1] * fb.y;
            }
        }
    }

    // scale + mask
#pragma unroll
    for (int gi = 0; gi < 8; gi++) {
        sA[gi] = sA[gi] * 0.125f + mfA[gi];
        sB[gi] = sB[gi] * 0.125f + mfB[gi];
    }

    // ---- softmax (row = h; 2 lanes per row), interleaved ----
    float mxA = sA[0], mxB = sB[0];
#pragma unroll
    for (int gi = 1; gi < 8; gi++) {
        mxA = fmaxf(mxA, sA[gi]);
        mxB = fmaxf(mxB, sB[gi]);
    }
    mxA = fmaxf(mxA, __shfl_xor_sync(0xffffffff, mxA, 1));
    mxB = fmaxf(mxB, __shfl_xor_sync(0xffffffff, mxB, 1));

    float eA[8], eB[8], sumA = 0.0f, sumB = 0.0f;
#pragma unroll
    for (int gi = 0; gi < 8; gi++) {
        eA[gi] = __expf(sA[gi] - mxA); sumA += eA[gi];
        eB[gi] = __expf(sB[gi] - mxB); sumB += eB[gi];
    }
    sumA += __shfl_xor_sync(0xffffffff, sumA, 1);
    sumB += __shfl_xor_sync(0xffffffff, sumB, 1);
    const float invA = 1.0f / sumA;
    const float invB = 1.0f / sumB;

    // full 16-wide weight vectors via partner exchange (lane^1 has other half)
    float wA[16], wB[16];
#pragma unroll
    for (int gi = 0; gi < 8; gi++) {
        const float oa = eA[gi] * invA;
        const float ob = eB[gi] * invB;
        const float pa = __shfl_xor_sync(0xffffffff, oa, 1);
        const float pb = __shfl_xor_sync(0xffffffff, ob, 1);
        // own half occupies [gh*8 + gi]; partner's occupies [(1-gh)*8 + gi]
        wA[gh * 8 + gi] = oa;  wA[(1 - gh) * 8 + gi] = pa;
        wB[gh * 8 + gi] = ob;  wB[(1 - gh) * 8 + gi] = pb;
    }

    // ---- PV interleaved: lane computes out[h][gh*32 .. gh*32+31] ----
    float accA[32], accB[32];
#pragma unroll
    for (int d = 0; d < 32; d++) { accA[d] = 0.0f; accB[d] = 0.0f; }

#pragma unroll
    for (int g = 0; g < 16; g++) {
        const float wvA = wA[g];
        const float wvB = wB[g];
        const __half* vA = smA + 2304 + g * 72 + gh * 32;
        const __half* vB = smB + 2304 + g * 72 + gh * 32;
#pragma unroll
        for (int d8 = 0; d8 < 4; d8++) {
            uint4 va = *(const uint4*)(vA + d8 * 8);
            uint4 vb = *(const uint4*)(vB + d8 * 8);
            const __half2* va2 = (const __half2*)&va;
            const __half2* vb2 = (const __half2*)&vb;
#pragma unroll
            for (int j = 0; j < 4; j++) {
                float2 fa = __half22float2(va2[j]);
                float2 fb = __half22float2(vb2[j]);
                accA[d8*8 + 2*j]   += wvA * fa.x;
                accA[d8*8 + 2*j+1] += wvA * fa.y;
                accB[d8*8 + 2*j]   += wvB * fb.x;
                accB[d8*8 + 2*j+1] += wvB * fb.y;
            }
        }
    }

    // ---- stores ----
    float* oA = out + (size_t)pA * HID + h * DH + gh * 32;
    float* oB = out + (size_t)pB * HID + h * DH + gh * 32;
#pragma unroll
    for (int d4 = 0; d4 < 8; d4++) {
        float4 a, b;
        a.x = accA[4*d4]; a.y = accA[4*d4+1]; a.z = accA[4*d4+2]; a.w = accA[4*d4+3];
        b.x = accB[4*d4]; b.y = accB[4*d4+1]; b.z = accB[4*d4+2]; b.w = accB[4*d4+3];
        *(float4*)(oA + 4*d4) = a;
        *(float4*)(oB + 4*d4) = b;
    }
}

// ---------------------------------------------------------------------------
// Launch — inputs: 0=query, 1=key, 2=value, 3=attn_mask, 4=W_qkv, 5=b_qkv
// ---------------------------------------------------------------------------
extern "C" void kernel_launch(void* const* d_in, const int* in_sizes, int n_in,
                              void* d_out, int out_size)
{
    const float* query = (const float*)d_in[0];
    const float* mask  = (const float*)d_in[3];
    const float* W     = (const float*)d_in[4];
    const float* bias  = (const float*)d_in[5];
    float* out = (float*)d_out;

    __half *qkv, *ah, *wh;
    cudaGetSymbolAddress((void**)&qkv, g_qkv);
    cudaGetSymbolAddress((void**)&ah, g_ah);
    cudaGetSymbolAddress((void**)&wh, g_wh);

    const int cvt_blocks = (int)((N4_TOTAL + 255) / 256);
    convert_kernel<<<cvt_blocks, 256>>>(query, W);

    cudaFuncSetAttribute(gemm_qkv_mma, cudaFuncAttributeMaxDynamicSharedMemorySize,
                         GEMM_SMEM);
    dim3 ggrid(N_TOT / 128, M_TOT / 128);  // (24, 128)
    gemm_qkv_mma<<<ggrid, 128, GEMM_SMEM>>>(ah, wh, bias, qkv);

    attn_kernel<<<M_TOT / 8, 128>>>(qkv, mask, out);
}

// round 15
// speedup vs baseline: 1.0554x; 1.0138x over previous
#include <cuda_runtime.h>
#include <cuda_fp16.h>
#include <cstdint>
#include <math.h>

// ---------------------------------------------------------------------------
// Problem constants
// ---------------------------------------------------------------------------
#define BATCH 4
#define SEQ   4096
#define HID   1024
#define NH    16
#define DH    64
#define M_TOT (BATCH * SEQ)   // 16384
#define N_TOT (3 * HID)       // 3072
#define K_TOT HID             // 1024

// Scratch (device globals: allocation-free rule)
__device__ __half g_qkv[(size_t)M_TOT * N_TOT];  // 96 MB
__device__ __half g_ah[(size_t)M_TOT * K_TOT];   // 32 MB
__device__ __half g_wh[(size_t)N_TOT * K_TOT];   // 6 MB

// ---------------------------------------------------------------------------
// Helpers (sm_80-era PTX only)
// ---------------------------------------------------------------------------
__device__ __forceinline__ uint32_t smem_u32(const void* p) {
    uint32_t a;
    asm("{ .reg .u64 t; cvta.to.shared.u64 t, %1; cvt.u32.u64 %0, t; }"
        : "=r"(a) : "l"(p));
    return a;
}

__device__ __forceinline__ void cp_async16(uint32_t s, const void* g) {
    asm volatile("cp.async.cg.shared.global [%0], [%1], 16;" :: "r"(s), "l"(g) : "memory");
}

__device__ __forceinline__ void ldsm_x4(uint32_t& r0, uint32_t& r1,
                                        uint32_t& r2, uint32_t& r3, uint32_t addr) {
    asm volatile("ldmatrix.sync.aligned.m8n8.x4.shared.b16 {%0,%1,%2,%3}, [%4];"
                 : "=r"(r0), "=r"(r1), "=r"(r2), "=r"(r3) : "r"(addr));
}

__device__ __forceinline__ void mma_fp16(float* c, const uint32_t* a,
                                         uint32_t b0, uint32_t b1) {
    asm volatile(
        "mma.sync.aligned.m16n8k16.row.col.f32.f16.f16.f32 "
        "{%0,%1,%2,%3}, {%4,%5,%6,%7}, {%8,%9}, {%0,%1,%2,%3};"
        : "+f"(c[0]), "+f"(c[1]), "+f"(c[2]), "+f"(c[3])
        : "r"(a[0]), "r"(a[1]), "r"(a[2]), "r"(a[3]), "r"(b0), "r"(b1));
}

// ---------------------------------------------------------------------------
// Conversion: A(fp32) -> fp16, W(fp32) -> fp16
// ---------------------------------------------------------------------------
#define N4_A ((size_t)M_TOT * K_TOT / 4)
#define N4_W ((size_t)N_TOT * K_TOT / 4)
#define N4_TOTAL (N4_A + N4_W)

__global__ __launch_bounds__(256) void convert_kernel(
    const float* __restrict__ A, const float* __restrict__ W)
{
    size_t idx = (size_t)blockIdx.x * blockDim.x + threadIdx.x;
    if (idx >= N4_TOTAL) return;

    if (idx < N4_A) {
        float4 v = ((const float4*)A)[idx];
        __half h[4] = { __float2half_rn(v.x), __float2half_rn(v.y),
                        __float2half_rn(v.z), __float2half_rn(v.w) };
        *(uint2*)(g_ah + idx * 4) = *(uint2*)h;
    } else {
        size_t j = idx - N4_A;
        float4 v = ((const float4*)W)[j];
        __half h[4] = { __float2half_rn(v.x), __float2half_rn(v.y),
                        __float2half_rn(v.z), __float2half_rn(v.w) };
        *(uint2*)(g_wh + j * 4) = *(uint2*)h;
    }
}

// ---------------------------------------------------------------------------
// GEMM fp16 (R12 form — at the legacy-HMMA dispatch rate; unchanged):
// CTA 128x128, 4 warps of 64x64, BK=64, 3 stages, 2 CTAs/SM.
// ---------------------------------------------------------------------------
#define BK      64
#define KITERS  (K_TOT / BK)     // 16
#define STAGES  3
#define ROWB    144
#define TILEB   (128 * ROWB)     // 18432
#define STAGEB  (2 * TILEB)      // 36864
#define GEMM_SMEM (STAGES * STAGEB)  // 110592

__global__ void __launch_bounds__(128, 2) gemm_qkv_mma(
    const __half* __restrict__ Ah, const __half* __restrict__ Wh,
    const float* __restrict__ bias, __half* __restrict__ C)
{
    extern __shared__ char smem[];
    const uint32_t sb = smem_u32(smem);
    const int t    = threadIdx.x;
    const int wid  = t >> 5;
    const int lane = t & 31;
    const int m0 = blockIdx.y * 128;
    const int n0 = blockIdx.x * 128;
    const int wm = (wid & 1) * 64;
    const int wn = (wid >> 1) * 64;

    const char* aptr = (const char*)(Ah + (size_t)(m0 + (t >> 3)) * K_TOT) + (t & 7) * 16;
    const char* wptr = (const char*)(Wh + (size_t)(n0 + (t >> 3)) * K_TOT) + (t & 7) * 16;
    const uint32_t so0 = (uint32_t)((t >> 3) * ROWB + (t & 7) * 16);

    auto load_stage = [&](int s) {
        const uint32_t dst = sb + (s % STAGES) * STAGEB + so0;
        const int koff = s * (BK * 2);
#pragma unroll
        for (int i = 0; i < 8; i++) {
            cp_async16(dst + (uint32_t)(i * 16 * ROWB),
                       aptr + (size_t)i * 16 * K_TOT * 2 + koff);
            cp_async16(dst + TILEB + (uint32_t)(i * 16 * ROWB),
                       wptr + (size_t)i * 16 * K_TOT * 2 + koff);
        }
    };

    float acc[4][8][4];
#pragma unroll
    for (int mt = 0; mt < 4; mt++)
#pragma unroll
        for (int nt = 0; nt < 8; nt++)
#pragma unroll
            for (int q = 0; q < 4; q++) acc[mt][nt][q] = 0.0f;

#pragma unroll
    for (int s = 0; s < STAGES - 1; s++) {
        load_stage(s);
        asm volatile("cp.async.commit_group;" ::: "memory");
    }

    const int lrow  = lane & 15;
    const int lkoff = (lane >> 4) * 16;

    for (int kit = 0; kit < KITERS; kit++) {
        asm volatile("cp.async.wait_group %0;" :: "n"(STAGES - 2) : "memory");
        __syncthreads();

        if (kit + STAGES - 1 < KITERS) load_stage(kit + STAGES - 1);
        asm volatile("cp.async.commit_group;" ::: "memory");

        const uint32_t bufb = sb + (kit % STAGES) * STAGEB;
        const uint32_t aH = bufb;
        const uint32_t wH = bufb + TILEB;

#pragma unroll
        for (int ks = 0; ks < 4; ks++) {
            const uint32_t kb = (uint32_t)(ks * 32 + lkoff);

            uint32_t af[4][4];
#pragma unroll
            for (int mt = 0; mt < 4; mt++) {
                const uint32_t ro = (uint32_t)((wm + mt * 16 + lrow) * ROWB) + kb;
                ldsm_x4(af[mt][0], af[mt][1], af[mt][2], af[mt][3], aH + ro);
            }

            uint32_t bh0[8], bh1[8];
#pragma unroll
            for (int np = 0; np < 4; np++) {
                const uint32_t ro = (uint32_t)((wn + np * 16 + lrow) * ROWB) + kb;
                uint32_t r0, r1, r2, r3;
                ldsm_x4(r0, r1, r2, r3, wH + ro);
                bh0[np * 2] = r0; bh1[np * 2] = r2;
                bh0[np * 2 + 1] = r1; bh1[np * 2 + 1] = r3;
            }

#pragma unroll
            for (int mt = 0; mt < 4; mt++)
#pragma unroll
                for (int nt = 0; nt < 8; nt++)
                    mma_fp16(acc[mt][nt], af[mt], bh0[nt], bh1[nt]);
        }
    }

#pragma unroll
    for (int mt = 0; mt < 4; mt++) {
        const int r = m0 + wm + mt * 16 + (lane >> 2);
#pragma unroll
        for (int nt = 0; nt < 8; nt++) {
            const int cc = n0 + wn + nt * 8 + (lane & 3) * 2;
            const float bx = __ldg(bias + cc);
            const float by = __ldg(bias + cc + 1);
            __half2 h0, h1;
            h0.x = __float2half_rn(acc[mt][nt][0] + bx);
            h0.y = __float2half_rn(acc[mt][nt][1] + by);
            h1.x = __float2half_rn(acc[mt][nt][2] + bx);
            h1.y = __float2half_rn(acc[mt][nt][3] + by);
            *(__half2*)(C + (size_t)r * N_TOT + cc)       = h0;
            *(__half2*)(C + (size_t)(r + 8) * N_TOT + cc) = h1;
        }
    }
}

// ---------------------------------------------------------------------------
// Attention v5: R8 body, register-trimmed for occupancy.
// - PV split into two d-halves: acc[16] (was acc[32])
// - e[] reuses s[]
// - __launch_bounds__(128, 7): <=73 regs, 7 blocks/SM (smem limit), 28 warps/SM
// Per-position arithmetic order identical to R8 -> identical numerics.
// ---------------------------------------------------------------------------
__global__ __launch_bounds__(128, 7) void attn_kernel(
    const __half* __restrict__ qkv, const float* __restrict__ mask,
    float* __restrict__ out)
{
    __shared__ __align__(16) unsigned char sm[4][8000];

    const int wid  = threadIdx.x >> 5;
    const int lane = threadIdx.x & 31;
    const int p = blockIdx.x * 4 + wid;

    __half* sqkv = (__half*)sm[wid];                 // arr*1152 + row*72 + d
    float*  sw   = (float*)(sm[wid] + 6912);         // [16][17]

    // Load 3072 halfs = 384 uint4; 12 per lane
    {
        const uint4* src = (const uint4*)(qkv + (size_t)p * N_TOT);
#pragma unroll
        for (int i = lane; i < 384; i += 32) {
            uint4 raw = src[i];
            const int e = i * 8;
            const int arr = e >> 10;          // 0=q, 1=k, 2=v
            const int r   = e & 1023;
            *(uint4*)(sqkv + arr * 1152 + (r >> 6) * 72 + (r & 63)) = raw;
        }
    }
    __syncwarp();

    const int h  = lane >> 1;
    const int gh = lane & 1;

    // ---- QK: 8 dot products of length 64 ----
    float s[8];
#pragma unroll
    for (int gi = 0; gi < 8; gi++) s[gi] = 0.0f;

    const __half* qrow = sqkv + h * 72;
#pragma unroll
    for (int d8 = 0; d8 < 8; d8++) {
        uint4 qraw = *(const uint4*)(qrow + d8 * 8);
        const __half2* qh2 = (const __half2*)&qraw;
        float qf[8];
#pragma unroll
        for (int j = 0; j < 4; j++) {
            float2 f = __half22float2(qh2[j]);
            qf[2 * j] = f.x; qf[2 * j + 1] = f.y;
        }
#pragma unroll
        for (int gi = 0; gi < 8; gi++) {
            const __half* krow = sqkv + 1152 + (gh * 8 + gi) * 72;
            uint4 kraw = *(const uint4*)(krow + d8 * 8);
            const __half2* kh2 = (const __half2*)&kraw;
#pragma unroll
            for (int j = 0; j < 4; j++) {
                float2 f = __half22float2(kh2[j]);
                s[gi] += qf[2 * j] * f.x + qf[2 * j + 1] * f.y;
            }
        }
    }

    // scale + mask (transient mask regs)
    {
        const float* mrow = mask + (size_t)p * (NH * NH) + h * NH + gh * 8;
        float4 m0 = *(const float4*)mrow;
        float4 m1 = *(const float4*)(mrow + 4);
        s[0] = s[0] * 0.125f + m0.x; s[1] = s[1] * 0.125f + m0.y;
        s[2] = s[2] * 0.125f + m0.z; s[3] = s[3] * 0.125f + m0.w;
        s[4] = s[4] * 0.125f + m1.x; s[5] = s[5] * 0.125f + m1.y;
        s[6] = s[6] * 0.125f + m1.z; s[7] = s[7] * 0.125f + m1.w;
    }

    // ---- softmax across the 16-wide row (2 lanes per row) ----
    float mx = s[0];
#pragma unroll
    for (int gi = 1; gi < 8; gi++) mx = fmaxf(mx, s[gi]);
    mx = fmaxf(mx, __shfl_xor_sync(0xffffffff, mx, 1));

    float sum = 0.0f;
#pragma unroll
    for (int gi = 0; gi < 8; gi++) { s[gi] = __expf(s[gi] - mx); sum += s[gi]; }
    sum += __shfl_xor_sync(0xffffffff, sum, 1);
    const float inv = 1.0f / sum;

#pragma unroll
    for (int gi = 0; gi < 8; gi++) sw[h * 17 + gh * 8 + gi] = s[gi] * inv;
    __syncwarp();

    // ---- PV in two d-halves of 16: acc[16] regs ----
    float* orow = out + (size_t)p * HID + h * DH + gh * 32;
#pragma unroll
    for (int dhf = 0; dhf < 2; dhf++) {
        float acc[16];
#pragma unroll
        for (int d = 0; d < 16; d++) acc[d] = 0.0f;

#pragma unroll
        for (int g = 0; g < 16; g++) {
            const float wv = sw[h * 17 + g];
            const __half* vrow = sqkv + 2304 + g * 72 + gh * 32 + dhf * 16;
#pragma unroll
            for (int d8 = 0; d8 < 2; d8++) {
                uint4 vr = *(const uint4*)(vrow + d8 * 8);
                const __half2* vh2 = (const __half2*)&vr;
#pragma unroll
                for (int j = 0; j < 4; j++) {
                    float2 f = __half22float2(vh2[j]);
                    acc[d8 * 8 + 2 * j]     += wv * f.x;
                    acc[d8 * 8 + 2 * j + 1] += wv * f.y;
                }
            }
        }

#pragma unroll
        for (int d4 = 0; d4 < 4; d4++) {
            float4 o;
            o.x = acc[4 * d4]; o.y = acc[4 * d4 + 1];
            o.z = acc[4 * d4 + 2]; o.w = acc[4 * d4 + 3];
            *(float4*)(orow + dhf * 16 + 4 * d4) = o;
        }
    }
}

// ---------------------------------------------------------------------------
// Launch — inputs: 0=query, 1=key, 2=value, 3=attn_mask, 4=W_qkv, 5=b_qkv
// ---------------------------------------------------------------------------
extern "C" void kernel_launch(void* const* d_in, const int* in_sizes, int n_in,
                              void* d_out, int out_size)
{
    const float* query = (const float*)d_in[0];
    const float* mask  = (const float*)d_in[3];
    const float* W     = (const float*)d_in[4];
    const float* bias  = (const float*)d_in[5];
    float* out = (float*)d_out;

    __half *qkv, *ah, *wh;
    cudaGetSymbolAddress((void**)&qkv, g_qkv);
    cudaGetSymbolAddress((void**)&ah, g_ah);
    cudaGetSymbolAddress((void**)&wh, g_wh);

    const int cvt_blocks = (int)((N4_TOTAL + 255) / 256);
    convert_kernel<<<cvt_blocks, 256>>>(query, W);

    cudaFuncSetAttribute(gemm_qkv_mma, cudaFuncAttributeMaxDynamicSharedMemorySize,
                         GEMM_SMEM);
    dim3 ggrid(N_TOT / 128, M_TOT / 128);  // (24, 128)
    gemm_qkv_mma<<<ggrid, 128, GEMM_SMEM>>>(ah, wh, bias, qkv);

    attn_kernel<<<M_TOT / 4, 128>>>(qkv, mask, out);
}